// round 16
// baseline (speedup 1.0000x reference)
#include <cuda_runtime.h>
#include <math.h>

// d(x,y) = a*dy^2 + b*dx^2 + c*dy*dx ; m = max(1-d,0)
// expanded: d = a y^2 + b x^2 + c x y + D y + E x + F
// record: A=(nb,nc,nE,na)  B=(nD,F1,wr,wg)  wb  (nb=-b etc., F1=1-F)
// render per (row,pt): ng = nc*y + nE ; h1 = (na*y + nD)*y + F1
// tile cull (sqrt/div-free, conservative): det = ab - c^2/4
//   max(|ly-yc|-hy,0)^2 * det <= b  AND  max(|lx-xc|-hx,0)^2 * det <= a

#define TW  32        // tile width  (pixels)  -- square tile minimizes overlap
#define TH  32        // tile height (rows)
#define TPB 256       // 8 threads/row, 4 consecutive px per thread
#define KPT 2         // prep points per thread (covers P <= 512)

__device__ __forceinline__ float sigm4(float v) {
    // sigmoid(4v) = 0.5*tanh(2v) + 0.5  -> 1x MUFU.TANH + FMUL + FFMA
    float t;
    asm("tanh.approx.f32 %0, %1;" : "=f"(t) : "f"(2.0f * v));
    return fmaf(0.5f, t, 0.5f);
}

__global__ __launch_bounds__(TPB)
void fused_kernel(const float* __restrict__ loc,
                  const float* __restrict__ moff,
                  const float* __restrict__ msfo,
                  const float* __restrict__ colors,
                  const float* __restrict__ alphas,
                  float* __restrict__ out,
                  int H, int W, int P, float ratio)
{
    extern __shared__ float smem[];
    float4* s_A  = (float4*)smem;              // P float4
    float4* s_B  = s_A + P;                    // P float4
    float*  s_wb = (float*)(s_B + P);          // P floats
    __shared__ int s_cnt;

    const int tid  = threadIdx.x;
    const int lane = tid & 31;
    if (tid == 0) s_cnt = 0;
    __syncthreads();

    // ---- Tile geometry ----
    const float dyp = 2.0f / (float)(H - 1);
    const float dxp = 2.0f * ratio / (float)(W - 1);
    const int tx = blockIdx.x, ty = blockIdx.y;

    const float hy = 0.5f * (float)(TH - 1) * dyp;
    const float hx = 0.5f * (float)(TW - 1) * dxp;
    const float yc = -1.0f  + (float)(ty * TH) * dyp + hy;
    const float xc = -ratio + (float)(tx * TW) * dxp + hx;

    const float sP = 0.5f * sqrtf((float)P);

    // ---- Phase 1: ALL loads for both points hoisted into one batch ----
    float  ms[KPT];
    float4 m4[KPT];
    float2 l2[KPT];
    float  c0[KPT], c1[KPT], c2[KPT], al[KPT];
    bool   inb[KPT];
#pragma unroll
    for (int k = 0; k < KPT; k++) {
        const int p = tid + k * TPB;
        inb[k] = (p < P);
        const int pc = inb[k] ? p : 0;      // clamp (P>=1) to keep loads safe
        ms[k] = __ldg(msfo + pc);
        m4[k] = __ldg((const float4*)moff + pc);
        l2[k] = __ldg((const float2*)loc + pc);
        c0[k] = __ldg(colors + 3 * pc + 0);
        c1[k] = __ldg(colors + 3 * pc + 1);
        c2[k] = __ldg(colors + 3 * pc + 2);
        al[k] = __ldg(alphas + pc);
    }

    // cull both points, then ONE fused compaction (single atomic + shfl)
    bool  act[KPT];
    float aa[KPT], bb[KPT], cc[KPT], ly[KPT], lx[KPT];
#pragma unroll
    for (int k = 0; k < KPT; k++) {
        act[k] = false;
        aa[k] = 0.f; bb[k] = 0.f; cc[k] = 0.f; ly[k] = 0.f; lx[k] = 0.f;
        if (inb[k]) {
            float scale = sP * __expf(ms[k]);
            float T00 = m4[k].x + scale, T01 = m4[k].y;
            float T10 = m4[k].z,         T11 = m4[k].w + scale;

            float a = T00 * T00 + T01 * T01;
            float b = T10 * T10 + T11 * T11;
            float c = 2.0f * (T00 * T10 + T01 * T11);
            float lly = l2[k].x, llx = l2[k].y;

            float det = fmaf(a, b, -0.25f * c * c);
            float tdy = fmaxf(fabsf(lly - yc) - hy, 0.0f);
            float tdx = fmaxf(fabsf(llx - xc) - hx, 0.0f);
            act[k] = (tdy * tdy * det <= b) && (tdx * tdx * det <= a);
            aa[k] = a; bb[k] = b; cc[k] = c; ly[k] = lly; lx[k] = llx;
        }
    }

    unsigned msk0 = __ballot_sync(0xffffffffu, act[0]);
    unsigned msk1 = __ballot_sync(0xffffffffu, act[1]);
    int total = __popc(msk0) + __popc(msk1);
    int base = 0;
    if (lane == 0 && total) base = atomicAdd(&s_cnt, total);
    base = __shfl_sync(0xffffffffu, base, 0);

    int pos[KPT];
    pos[0] = base + __popc(msk0 & ((1u << lane) - 1u));
    pos[1] = base + __popc(msk0) + __popc(msk1 & ((1u << lane) - 1u));

#pragma unroll
    for (int k = 0; k < KPT; k++) {
        if (act[k]) {
            float a = aa[k], b = bb[k], c = cc[k];
            float D = -(2.0f * a * ly[k] + c * lx[k]);
            float E = -(2.0f * b * lx[k] + c * ly[k]);
            float F = a * ly[k] * ly[k] + b * lx[k] * lx[k] + c * lx[k] * ly[k];
            float wr = c0[k] * al[k];
            float wg = c1[k] * al[k];
            float wb = c2[k] * al[k];
            s_A[pos[k]]  = make_float4(-b, -c, -E, -a);
            s_B[pos[k]]  = make_float4(-D, 1.0f - F, wr, wg);
            s_wb[pos[k]] = wb;
        }
    }
    __syncthreads();
    const int count = s_cnt;

    // ---- Phase 2: render 4 consecutive px/thread; 8 threads per row ----
    const int rowi = tid >> 3;                 // 0..TH-1
    const int coli = (tid & 7) * 4;            // 0,4,...,28
    const int gy = ty * TH + rowi;
    const int gx = tx * TW + coli;
    const float y  = -1.0f  + (float)gy * dyp;
    const float x0 = -ratio + (float)gx * dxp;
    const float x1 = x0 + dxp, x2 = x1 + dxp, x3 = x2 + dxp;

    float ar0 = 0.f, ag0 = 0.f, ab0 = 0.f;
    float ar1 = 0.f, ag1 = 0.f, ab1 = 0.f;
    float ar2 = 0.f, ag2 = 0.f, ab2 = 0.f;
    float ar3 = 0.f, ag3 = 0.f, ab3 = 0.f;

#pragma unroll 4
    for (int p = 0; p < count; p++) {
        const float4 rA = s_A[p];
        const float4 rB = s_B[p];
        const float  wb = s_wb[p];

        float ng = fmaf(y, rA.y, rA.z);                   // nc*y + nE
        float h1 = fmaf(y, fmaf(y, rA.w, rB.x), rB.y);    // (na*y+nD)*y + F1

        float m0 = fmaxf(fmaf(x0, fmaf(x0, rA.x, ng), h1), 0.0f);
        float m1 = fmaxf(fmaf(x1, fmaf(x1, rA.x, ng), h1), 0.0f);
        float m2 = fmaxf(fmaf(x2, fmaf(x2, rA.x, ng), h1), 0.0f);
        float m3 = fmaxf(fmaf(x3, fmaf(x3, rA.x, ng), h1), 0.0f);

        ar0 = fmaf(m0, rB.z, ar0);  ar1 = fmaf(m1, rB.z, ar1);
        ar2 = fmaf(m2, rB.z, ar2);  ar3 = fmaf(m3, rB.z, ar3);
        ag0 = fmaf(m0, rB.w, ag0);  ag1 = fmaf(m1, rB.w, ag1);
        ag2 = fmaf(m2, rB.w, ag2);  ag3 = fmaf(m3, rB.w, ag3);
        ab0 = fmaf(m0, wb,  ab0);   ab1 = fmaf(m1, wb,  ab1);
        ab2 = fmaf(m2, wb,  ab2);   ab3 = fmaf(m3, wb,  ab3);
    }

    // ---- sigmoid(4*canvas) epilogue; 12 floats = 3x STG.128 ----
    if (gy < H && gx + 3 < W) {
        float4 o0 = make_float4(sigm4(ar0), sigm4(ag0), sigm4(ab0), sigm4(ar1));
        float4 o1 = make_float4(sigm4(ag1), sigm4(ab1), sigm4(ar2), sigm4(ag2));
        float4 o2 = make_float4(sigm4(ab2), sigm4(ar3), sigm4(ag3), sigm4(ab3));
        float4* o = (float4*)(out + ((size_t)gy * W + gx) * 3);
        o[0] = o0; o[1] = o1; o[2] = o2;
    }
}

// ---- Fallback for P > KPT*TPB: strided prep (same structure, looped) ----
__global__ __launch_bounds__(TPB)
void fused_fallback(const float* __restrict__ loc,
                    const float* __restrict__ moff,
                    const float* __restrict__ msfo,
                    const float* __restrict__ colors,
                    const float* __restrict__ alphas,
                    float* __restrict__ out,
                    int H, int W, int P, float ratio)
{
    extern __shared__ float smem[];
    float4* s_A  = (float4*)smem;
    float4* s_B  = s_A + P;
    float*  s_wb = (float*)(s_B + P);
    __shared__ int s_cnt;

    const int tid  = threadIdx.x;
    const int lane = tid & 31;
    if (tid == 0) s_cnt = 0;
    __syncthreads();

    const float dyp = 2.0f / (float)(H - 1);
    const float dxp = 2.0f * ratio / (float)(W - 1);
    const int tx = blockIdx.x, ty = blockIdx.y;
    const float hy = 0.5f * (float)(TH - 1) * dyp;
    const float hx = 0.5f * (float)(TW - 1) * dxp;
    const float yc = -1.0f  + (float)(ty * TH) * dyp + hy;
    const float xc = -ratio + (float)(tx * TW) * dxp + hx;
    const float sP = 0.5f * sqrtf((float)P);

    for (int p0 = 0; p0 < P; p0 += TPB) {
        const int p = p0 + tid;
        bool act = false;
        float a = 0.f, b = 0.f, c = 0.f, ly = 0.f, lx = 0.f;
        float wr = 0.f, wg = 0.f, wb = 0.f;
        if (p < P) {
            float  ms = __ldg(msfo + p);
            float4 m4 = __ldg((const float4*)moff + p);
            float2 l2 = __ldg((const float2*)loc + p);
            float  c0 = __ldg(colors + 3 * p + 0);
            float  c1 = __ldg(colors + 3 * p + 1);
            float  c2 = __ldg(colors + 3 * p + 2);
            float  al = __ldg(alphas + p);
            float scale = sP * __expf(ms);
            float T00 = m4.x + scale, T01 = m4.y;
            float T10 = m4.z,         T11 = m4.w + scale;
            a = T00 * T00 + T01 * T01;
            b = T10 * T10 + T11 * T11;
            c = 2.0f * (T00 * T10 + T01 * T11);
            ly = l2.x; lx = l2.y;
            float det = fmaf(a, b, -0.25f * c * c);
            float tdy = fmaxf(fabsf(ly - yc) - hy, 0.0f);
            float tdx = fmaxf(fabsf(lx - xc) - hx, 0.0f);
            act = (tdy * tdy * det <= b) && (tdx * tdx * det <= a);
            wr = c0 * al; wg = c1 * al; wb = c2 * al;
        }
        unsigned msk = __ballot_sync(0xffffffffu, act);
        if (msk) {
            int leader = __ffs(msk) - 1;
            int b0 = 0;
            if (lane == leader) b0 = atomicAdd(&s_cnt, __popc(msk));
            b0 = __shfl_sync(0xffffffffu, b0, leader);
            int pos = b0 + __popc(msk & ((1u << lane) - 1u));
            if (act) {
                float D = -(2.0f * a * ly + c * lx);
                float E = -(2.0f * b * lx + c * ly);
                float F = a * ly * ly + b * lx * lx + c * lx * ly;
                s_A[pos]  = make_float4(-b, -c, -E, -a);
                s_B[pos]  = make_float4(-D, 1.0f - F, wr, wg);
                s_wb[pos] = wb;
            }
        }
    }
    __syncthreads();
    const int count = s_cnt;

    const int rowi = tid >> 3;
    const int coli = (tid & 7) * 4;
    const int gy = ty * TH + rowi;
    const int gx = tx * TW + coli;
    const float y  = -1.0f  + (float)gy * dyp;
    const float x0 = -ratio + (float)gx * dxp;
    const float x1 = x0 + dxp, x2 = x1 + dxp, x3 = x2 + dxp;

    float ar0 = 0.f, ag0 = 0.f, ab0 = 0.f;
    float ar1 = 0.f, ag1 = 0.f, ab1 = 0.f;
    float ar2 = 0.f, ag2 = 0.f, ab2 = 0.f;
    float ar3 = 0.f, ag3 = 0.f, ab3 = 0.f;

#pragma unroll 4
    for (int p = 0; p < count; p++) {
        const float4 rA = s_A[p];
        const float4 rB = s_B[p];
        const float  wb = s_wb[p];
        float ng = fmaf(y, rA.y, rA.z);
        float h1 = fmaf(y, fmaf(y, rA.w, rB.x), rB.y);
        float m0 = fmaxf(fmaf(x0, fmaf(x0, rA.x, ng), h1), 0.0f);
        float m1 = fmaxf(fmaf(x1, fmaf(x1, rA.x, ng), h1), 0.0f);
        float m2 = fmaxf(fmaf(x2, fmaf(x2, rA.x, ng), h1), 0.0f);
        float m3 = fmaxf(fmaf(x3, fmaf(x3, rA.x, ng), h1), 0.0f);
        ar0 = fmaf(m0, rB.z, ar0);  ar1 = fmaf(m1, rB.z, ar1);
        ar2 = fmaf(m2, rB.z, ar2);  ar3 = fmaf(m3, rB.z, ar3);
        ag0 = fmaf(m0, rB.w, ag0);  ag1 = fmaf(m1, rB.w, ag1);
        ag2 = fmaf(m2, rB.w, ag2);  ag3 = fmaf(m3, rB.w, ag3);
        ab0 = fmaf(m0, wb,  ab0);   ab1 = fmaf(m1, wb,  ab1);
        ab2 = fmaf(m2, wb,  ab2);   ab3 = fmaf(m3, wb,  ab3);
    }

    if (gy < H && gx + 3 < W) {
        float4 o0 = make_float4(sigm4(ar0), sigm4(ag0), sigm4(ab0), sigm4(ar1));
        float4 o1 = make_float4(sigm4(ag1), sigm4(ab1), sigm4(ar2), sigm4(ag2));
        float4 o2 = make_float4(sigm4(ab2), sigm4(ar3), sigm4(ag3), sigm4(ab3));
        float4* o = (float4*)(out + ((size_t)gy * W + gx) * 3);
        o[0] = o0; o[1] = o1; o[2] = o2;
    }
}

extern "C" void kernel_launch(void* const* d_in, const int* in_sizes, int n_in,
                              void* d_out, int out_size)
{
    const float* loc    = (const float*)d_in[2];
    const float* moff   = (const float*)d_in[3];
    const float* msfo   = (const float*)d_in[4];
    const float* colors = (const float*)d_in[5];
    const float* alphas = (const float*)d_in[6];
    float* out = (float*)d_out;

    int P = in_sizes[2] / 2;             // locations has P*2 elements
    int HW = out_size / 3;               // output is H*W*3
    int H = (int)(sqrt((double)HW) + 0.5);
    int W = HW / H;
    float ratio = (float)W / (float)H;

    size_t smem = (size_t)P * (2 * sizeof(float4) + sizeof(float)); // 18 KB @P=512
    dim3 grid((W + TW - 1) / TW, (H + TH - 1) / TH);

    if (P <= KPT * TPB) {
        cudaFuncSetAttribute(fused_kernel,
                             cudaFuncAttributeMaxDynamicSharedMemorySize, (int)smem);
        fused_kernel<<<grid, TPB, smem>>>(loc, moff, msfo, colors, alphas,
                                          out, H, W, P, ratio);
    } else {
        cudaFuncSetAttribute(fused_fallback,
                             cudaFuncAttributeMaxDynamicSharedMemorySize, (int)smem);
        fused_fallback<<<grid, TPB, smem>>>(loc, moff, msfo, colors, alphas,
                                            out, H, W, P, ratio);
    }
}